// round 2
// baseline (speedup 1.0000x reference)
#include <cuda_runtime.h>
#include <cuda_bf16.h>
#include <math.h>
#include <stdint.h>

// Problem constants (fixed by the dataset)
#define TT 5
#define FIN 10
#define HID 16
#define MAXN 100000
#define MAXE 3200000
#define XSTRIDE 52        // padded T*FIN (50 -> 52 so rows are 16B-multiple)
#define FSTRIDE 80        // T*HID

// ---------------- device scratch (static: no allocation allowed) ----------------
// .bss arrays are zero-initialized at module load; kernels restore any state they
// consume so every graph replay sees identical starting state.
__device__ int   g_cnt[MAXN];          // degree counters (zero at entry, re-zeroed in koffsets)
__device__ int   g_deg[MAXN];
__device__ int   g_row[MAXN];
__device__ int   g_cursor[MAXN];
__device__ int   g_total;              // reset by kcount thread 0
__device__ float g_dis[MAXN];
__device__ float g_dinv[MAXN];
__device__ int2  g_edge[MAXE];         // .x = src, .y = float bits of enorm
__device__ float g_xT[(size_t)MAXN * XSTRIDE];
__device__ float g_h1[(size_t)MAXN * FSTRIDE];
__device__ float g_feats[(size_t)MAXN * FSTRIDE];
__device__ float g_P[(size_t)MAXN * FSTRIDE];

// ---------------- stage -1: transpose x [T,N,F] -> xT [N, XSTRIDE] --------------
__global__ void kxt(const float* __restrict__ x, float* __restrict__ xT, int n) {
    int i = blockIdx.x * blockDim.x + threadIdx.x;
    if (i >= n * (TT * FIN)) return;
    int node = i / (TT * FIN);
    int c = i - node * (TT * FIN);
    int t = c / FIN;
    int f = c - t * FIN;
    xT[(size_t)node * XSTRIDE + c] = x[((size_t)t * n + node) * FIN + f];
}

// ---------------- CSR build (unordered slices) -----------------------------------
__global__ void kcount(const int* __restrict__ dst, int* cnt, int e) {
    int i = blockIdx.x * blockDim.x + threadIdx.x;
    if (i == 0) g_total = 0;
    if (i < e) atomicAdd(&cnt[dst[i]], 1);
}

// per-block scan + single atomic -> contiguous (unordered) slices per node
__global__ __launch_bounds__(256) void koffsets(int* cnt, int n) {
    __shared__ int sh[256];
    __shared__ int sbase;
    int tid = threadIdx.x;
    int i = blockIdx.x * 256 + tid;
    int deg = (i < n) ? cnt[i] : 0;
    sh[tid] = deg;
    __syncthreads();
    for (int off = 1; off < 256; off <<= 1) {
        int t = (tid >= off) ? sh[tid - off] : 0;
        __syncthreads();
        sh[tid] += t;
        __syncthreads();
    }
    if (tid == 255) sbase = atomicAdd(&g_total, sh[255]);
    __syncthreads();
    int start = sbase + sh[tid] - deg;
    if (i < n) {
        g_row[i]    = start;
        g_cursor[i] = start;
        g_deg[i]    = deg;
        cnt[i]      = 0;                 // restore for next graph replay
        float d = (float)deg + 1.0f;
        g_dis[i]  = rsqrtf(d);
        g_dinv[i] = 1.0f / d;
    }
}

__global__ void kfill(const int* __restrict__ src, const int* __restrict__ dst,
                      const float* __restrict__ dis, int* cursor, int2* edge, int e) {
    int i = blockIdx.x * blockDim.x + threadIdx.x;
    if (i < e) {
        int s = src[i], d = dst[i];
        int pos = atomicAdd(&cursor[d], 1);
        edge[pos] = make_int2(s, __float_as_int(dis[s] * dis[d]));
    }
}

// ---------------- propagation (+ optional fused dense transform) -----------------
// warp per destination node. lane l owns float4 columns [4l, 4l+4).
// STRIDE: input row stride in floats. NV4 = STRIDE/4 active lanes.
// FUSE: if >0, apply out = relu( (S in) @ W + b ) with W [FIN_IN x 16] per slice,
// writing FSTRIDE-wide rows. If 0, write the propagated row directly.
template <int STRIDE, int FIN_IN, int FUSE>
__global__ __launch_bounds__(256) void kprop(const float* __restrict__ in,
                                             float* __restrict__ out,
                                             const int* __restrict__ rowp,
                                             const int* __restrict__ degv,
                                             const int2* __restrict__ edge,
                                             const float* __restrict__ dinv,
                                             const float* __restrict__ Wm,
                                             const float* __restrict__ bm, int n) {
    constexpr int NV4 = STRIDE / 4;
    __shared__ float sAgg[8][STRIDE];
    __shared__ float sW[FUSE ? FIN_IN * 16 : 1];
    __shared__ float sB[FUSE ? 16 : 1];
    if (FUSE) {
        for (int i = threadIdx.x; i < FIN_IN * 16; i += blockDim.x) sW[i] = Wm[i];
        if (threadIdx.x < 16) sB[threadIdx.x] = bm[threadIdx.x];
        __syncthreads();
    }
    int wwid = threadIdx.x >> 5;
    int node = (blockIdx.x << 3) + wwid;
    if (node >= n) return;
    int lane = threadIdx.x & 31;

    float4 acc = make_float4(0.f, 0.f, 0.f, 0.f);

    int r0 = rowp[node];
    int deg = degv[node];
    int nfull = deg >> 5;
    int rem = deg & 31;

    const unsigned FULL = 0xffffffffu;

    // full 32-edge chunks with prefetch of the next chunk's metadata
    if (nfull) {
        int2 e = g_edge[r0 + lane];  // placeholder to establish type
        e = edge[r0 + lane];
        for (int c = 0; c < nfull; c++) {
            int2 enext = make_int2(0, 0);
            int nb = r0 + (c + 1) * 32;
            if (c + 1 < nfull) enext = edge[nb + lane];
            else if (lane < rem) enext = edge[nb + lane];
#pragma unroll 8
            for (int k = 0; k < 32; k++) {
                int   ss = __shfl_sync(FULL, e.x, k);
                float ww = __int_as_float(__shfl_sync(FULL, e.y, k));
                float4 v = make_float4(0.f, 0.f, 0.f, 0.f);
                if (lane < NV4)
                    v = __ldg((const float4*)(in + (size_t)ss * STRIDE) + lane);
                acc.x = fmaf(ww, v.x, acc.x);
                acc.y = fmaf(ww, v.y, acc.y);
                acc.z = fmaf(ww, v.z, acc.z);
                acc.w = fmaf(ww, v.w, acc.w);
            }
            e = enext;
        }
        // tail uses prefetched e
        if (rem) {
#pragma unroll 4
            for (int k = 0; k < 32; k++) {
                if (k >= rem) break;
                int   ss = __shfl_sync(FULL, e.x, k);
                float ww = __int_as_float(__shfl_sync(FULL, e.y, k));
                float4 v = make_float4(0.f, 0.f, 0.f, 0.f);
                if (lane < NV4)
                    v = __ldg((const float4*)(in + (size_t)ss * STRIDE) + lane);
                acc.x = fmaf(ww, v.x, acc.x);
                acc.y = fmaf(ww, v.y, acc.y);
                acc.z = fmaf(ww, v.z, acc.z);
                acc.w = fmaf(ww, v.w, acc.w);
            }
        }
    } else if (rem) {
        int2 e = make_int2(0, 0);
        if (lane < rem) e = edge[r0 + lane];
#pragma unroll 4
        for (int k = 0; k < 32; k++) {
            if (k >= rem) break;
            int   ss = __shfl_sync(FULL, e.x, k);
            float ww = __int_as_float(__shfl_sync(FULL, e.y, k));
            float4 v = make_float4(0.f, 0.f, 0.f, 0.f);
            if (lane < NV4)
                v = __ldg((const float4*)(in + (size_t)ss * STRIDE) + lane);
            acc.x = fmaf(ww, v.x, acc.x);
            acc.y = fmaf(ww, v.y, acc.y);
            acc.z = fmaf(ww, v.z, acc.z);
            acc.w = fmaf(ww, v.w, acc.w);
        }
    }

    // self-loop
    float di = dinv[node];
    if (lane < NV4) {
        float4 sv = __ldg((const float4*)(in + (size_t)node * STRIDE) + lane);
        acc.x = fmaf(di, sv.x, acc.x);
        acc.y = fmaf(di, sv.y, acc.y);
        acc.z = fmaf(di, sv.z, acc.z);
        acc.w = fmaf(di, sv.w, acc.w);
    }

    if (!FUSE) {
        if (lane < NV4)
            *((float4*)(out + (size_t)node * STRIDE) + lane) = acc;
        return;
    }

    // fused per-slice dense transform: out[t*16+h] = relu(b[h] + sum_f agg[t*FIN_IN+f]*W[f,h])
    if (lane < NV4) *(float4*)&sAgg[wwid][lane * 4] = acc;
    __syncwarp();
    if (lane < 20) {
        int c = lane * 4;
        int t = c >> 4;
        int h = c & 15;
        float o0 = sB[h], o1 = sB[h + 1], o2 = sB[h + 2], o3 = sB[h + 3];
#pragma unroll
        for (int f = 0; f < FIN_IN; f++) {
            float a = sAgg[wwid][t * FIN_IN + f];
            o0 = fmaf(a, sW[f * 16 + h], o0);
            o1 = fmaf(a, sW[f * 16 + h + 1], o1);
            o2 = fmaf(a, sW[f * 16 + h + 2], o2);
            o3 = fmaf(a, sW[f * 16 + h + 3], o3);
        }
        float4 ov = make_float4(fmaxf(o0, 0.f), fmaxf(o1, 0.f),
                                fmaxf(o2, 0.f), fmaxf(o3, 0.f));
        *((float4*)(out + (size_t)node * FSTRIDE) + lane) = ov;
    }
}

// ---------------- GRU + attention pooling + FC + log_softmax ---------------------
#define GRU_NPB 96
__global__ __launch_bounds__(GRU_NPB) void kgru(const float* __restrict__ P,
                                                const float* __restrict__ Wz,
                                                const float* __restrict__ bz,
                                                const float* __restrict__ Wr,
                                                const float* __restrict__ br,
                                                const float* __restrict__ Wh,
                                                const float* __restrict__ bh,
                                                const float* __restrict__ Lz,
                                                const float* __restrict__ lz,
                                                const float* __restrict__ Lr,
                                                const float* __restrict__ lr,
                                                const float* __restrict__ Lh,
                                                const float* __restrict__ lh,
                                                const float* __restrict__ att,
                                                const float* __restrict__ fcW,
                                                const float* __restrict__ fcb,
                                                float* __restrict__ out, int n) {
    __shared__ float sP[GRU_NPB * 81];
    __shared__ float sMz[256], sMr[256], sMh[256];
    __shared__ float sLz[256], sLr[256], sLh[256];
    __shared__ float sBz[16], sBr[16], sBh[16];
    __shared__ float sfcW[32], sfcb[2], sprob[TT];

    int tid = threadIdx.x;
    // fold the gate GCN weight matmuls into single 16x16 matrices:
    // concat([p@W*, H]) @ L* = p @ (W* @ L*[0:16]) + H @ L*[16:32]
    for (int i = tid; i < 256; i += GRU_NPB) {
        int k = i >> 4, h = i & 15;
        float mz = 0.f, mr = 0.f, mh = 0.f;
#pragma unroll
        for (int j = 0; j < 16; j++) {
            mz = fmaf(__ldg(&Wz[k * 16 + j]), __ldg(&Lz[j * 16 + h]), mz);
            mr = fmaf(__ldg(&Wr[k * 16 + j]), __ldg(&Lr[j * 16 + h]), mr);
            mh = fmaf(__ldg(&Wh[k * 16 + j]), __ldg(&Lh[j * 16 + h]), mh);
        }
        sMz[i] = mz; sMr[i] = mr; sMh[i] = mh;
        sLz[i] = __ldg(&Lz[256 + i]);
        sLr[i] = __ldg(&Lr[256 + i]);
        sLh[i] = __ldg(&Lh[256 + i]);
    }
    if (tid < 16) {
        float az = __ldg(&lz[tid]), ar = __ldg(&lr[tid]), ah = __ldg(&lh[tid]);
#pragma unroll
        for (int j = 0; j < 16; j++) {
            az = fmaf(__ldg(&bz[j]), __ldg(&Lz[j * 16 + tid]), az);
            ar = fmaf(__ldg(&br[j]), __ldg(&Lr[j * 16 + tid]), ar);
            ah = fmaf(__ldg(&bh[j]), __ldg(&Lh[j * 16 + tid]), ah);
        }
        sBz[tid] = az; sBr[tid] = ar; sBh[tid] = ah;
    }
    if (tid < 32) sfcW[tid] = __ldg(&fcW[tid]);
    if (tid < 2)  sfcb[tid] = __ldg(&fcb[tid]);
    if (tid == 0) {
        float m = att[0];
        for (int t = 1; t < TT; t++) m = fmaxf(m, att[t]);
        float ex[TT]; float s = 0.f;
        for (int t = 0; t < TT; t++) { ex[t] = expf(att[t] - m); s += ex[t]; }
        for (int t = 0; t < TT; t++) sprob[t] = ex[t] / s;
    }
    int base = blockIdx.x * GRU_NPB;
    for (int i = tid; i < GRU_NPB * FSTRIDE; i += GRU_NPB) {
        int nd = i / FSTRIDE, c = i - nd * FSTRIDE;
        int g = base + nd;
        sP[nd * 81 + c] = (g < n) ? P[(size_t)g * FSTRIDE + c] : 0.f;
    }
    __syncthreads();

    int node = base + tid;
    if (node >= n) return;
    const float* myP = &sP[tid * 81];

    float H[16], Hacc[16];
#pragma unroll
    for (int h = 0; h < 16; h++) { H[h] = 0.f; Hacc[h] = 0.f; }

#pragma unroll 1
    for (int t = 0; t < TT; t++) {
        float p[16];
#pragma unroll
        for (int k = 0; k < 16; k++) p[k] = myP[t * 16 + k];

        float a[16];
#pragma unroll
        for (int h = 0; h < 16; h++) a[h] = sBz[h];
#pragma unroll
        for (int k = 0; k < 16; k++) {
            float pk = p[k], hk = H[k];
#pragma unroll
            for (int h = 0; h < 16; h++)
                a[h] += pk * sMz[k * 16 + h] + hk * sLz[k * 16 + h];
        }
        float Zg[16];
#pragma unroll
        for (int h = 0; h < 16; h++) Zg[h] = 1.f / (1.f + expf(-a[h]));

#pragma unroll
        for (int h = 0; h < 16; h++) a[h] = sBr[h];
#pragma unroll
        for (int k = 0; k < 16; k++) {
            float pk = p[k], hk = H[k];
#pragma unroll
            for (int h = 0; h < 16; h++)
                a[h] += pk * sMr[k * 16 + h] + hk * sLr[k * 16 + h];
        }
        float Rg[16];
#pragma unroll
        for (int h = 0; h < 16; h++) Rg[h] = 1.f / (1.f + expf(-a[h]));

#pragma unroll
        for (int h = 0; h < 16; h++) a[h] = sBh[h];
#pragma unroll
        for (int k = 0; k < 16; k++) {
            float pk = p[k], hr = H[k] * Rg[k];
#pragma unroll
            for (int h = 0; h < 16; h++)
                a[h] += pk * sMh[k * 16 + h] + hr * sLh[k * 16 + h];
        }
#pragma unroll
        for (int h = 0; h < 16; h++) {
            float ht = tanhf(a[h]);
            H[h] = Zg[h] * H[h] + (1.f - Zg[h]) * ht;
            Hacc[h] = fmaf(sprob[t], H[h], Hacc[h]);
        }
    }

    float l0 = sfcb[0], l1 = sfcb[1];
#pragma unroll
    for (int h = 0; h < 16; h++) {
        l0 = fmaf(Hacc[h], sfcW[h * 2 + 0], l0);
        l1 = fmaf(Hacc[h], sfcW[h * 2 + 1], l1);
    }
    float m = fmaxf(l0, l1);
    float lse = m + logf(expf(l0 - m) + expf(l1 - m));
    out[(size_t)node * 2 + 0] = l0 - lse;
    out[(size_t)node * 2 + 1] = l1 - lse;
}

// ---------------- launch ----------------
extern "C" void kernel_launch(void* const* d_in, const int* in_sizes, int n_in,
                              void* d_out, int out_size) {
    const float* x   = (const float*)d_in[0];
    const int*   src = (const int*)d_in[1];
    const int*   dst = (const int*)d_in[2];
    const float* W1  = (const float*)d_in[3];
    const float* b1  = (const float*)d_in[4];
    const float* W2  = (const float*)d_in[5];
    const float* b2  = (const float*)d_in[6];
    const float* Wz  = (const float*)d_in[7];
    const float* bz  = (const float*)d_in[8];
    const float* Wr  = (const float*)d_in[9];
    const float* br  = (const float*)d_in[10];
    const float* Wh  = (const float*)d_in[11];
    const float* bh  = (const float*)d_in[12];
    const float* Lz  = (const float*)d_in[13];
    const float* lz  = (const float*)d_in[14];
    const float* Lr  = (const float*)d_in[15];
    const float* lr  = (const float*)d_in[16];
    const float* Lh  = (const float*)d_in[17];
    const float* lh  = (const float*)d_in[18];
    const float* att = (const float*)d_in[19];
    const float* fcW = (const float*)d_in[20];
    const float* fcb = (const float*)d_in[21];

    int n = in_sizes[0] / (TT * FIN);
    int e = in_sizes[1];

    void* p;
    cudaGetSymbolAddress(&p, g_cnt);     int*   cnt    = (int*)p;
    cudaGetSymbolAddress(&p, g_deg);     int*   degv   = (int*)p;
    cudaGetSymbolAddress(&p, g_row);     int*   rowp   = (int*)p;
    cudaGetSymbolAddress(&p, g_cursor);  int*   cursor = (int*)p;
    cudaGetSymbolAddress(&p, g_dis);     float* dis    = (float*)p;
    cudaGetSymbolAddress(&p, g_dinv);    float* dinv   = (float*)p;
    cudaGetSymbolAddress(&p, g_edge);    int2*  edge   = (int2*)p;
    cudaGetSymbolAddress(&p, g_xT);      float* xT     = (float*)p;
    cudaGetSymbolAddress(&p, g_h1);      float* h1     = (float*)p;
    cudaGetSymbolAddress(&p, g_feats);   float* feats  = (float*)p;
    cudaGetSymbolAddress(&p, g_P);       float* P      = (float*)p;

    int nb256_n = (n + 255) / 256;
    int nb256_e = (e + 255) / 256;
    int prop_blocks = (n + 7) / 8;

    // 0: transpose x (independent of CSR)
    kxt<<<(n * TT * FIN + 255) / 256, 256>>>(x, xT, n);
    // 1-3: CSR build
    kcount<<<nb256_e, 256>>>(dst, cnt, e);
    koffsets<<<nb256_n, 256>>>(cnt, n);
    kfill<<<nb256_e, 256>>>(src, dst, dis, cursor, edge, e);
    // 4: h1 = relu((S x) @ W1 + b1)
    kprop<XSTRIDE, FIN, 1><<<prop_blocks, 256>>>(xT, h1, rowp, degv, edge, dinv, W1, b1, n);
    // 5: feats = relu((S h1) @ W2 + b2)
    kprop<FSTRIDE, HID, 1><<<prop_blocks, 256>>>(h1, feats, rowp, degv, edge, dinv, W2, b2, n);
    // 6: P = S feats (shared by all three GRU gate GCNs)
    kprop<FSTRIDE, HID, 0><<<prop_blocks, 256>>>(feats, P, rowp, degv, edge, dinv, W2, b2, n);
    // 7: GRU + attention + FC + log_softmax
    kgru<<<(n + GRU_NPB - 1) / GRU_NPB, GRU_NPB>>>(P, Wz, bz, Wr, br, Wh, bh,
                                                   Lz, lz, Lr, lr, Lh, lh,
                                                   att, fcW, fcb, (float*)d_out, n);
}

// round 3
// speedup vs baseline: 1.3332x; 1.3332x over previous
#include <cuda_runtime.h>
#include <cuda_bf16.h>
#include <math.h>
#include <stdint.h>

// Problem constants (fixed by the dataset)
#define TT 5
#define FIN 10
#define HID 16
#define MAXN 100000
#define MAXE 3200000
#define XSTRIDE 52        // padded T*FIN (50 -> 52, 16B multiple)
#define XREAL  50
#define FSTRIDE 80        // T*HID

// ---------------- device scratch (static: no allocation allowed) ----------------
__device__ int   g_cnt[MAXN];          // zero at load; re-zeroed each call in koffsets
__device__ int   g_deg[MAXN];
__device__ int   g_row[MAXN];
__device__ int   g_cursor[MAXN];
__device__ int   g_total;
__device__ float g_dis[MAXN];
__device__ float g_dinv[MAXN];
__device__ int2  g_edge[MAXE];         // .x = src, .y = float bits of enorm
__device__ float g_xT[(size_t)MAXN * XSTRIDE];
__device__ float g_h1[(size_t)MAXN * FSTRIDE];
__device__ float g_feats[(size_t)MAXN * FSTRIDE];
__device__ float g_P[(size_t)MAXN * FSTRIDE];
__device__ float g_Mz[256], g_Mr[256], g_Mh[256];
__device__ float g_Bz[16],  g_Br[16],  g_Bh[16];

// ---------------- stage 0: fused degree count + x transpose ---------------------
// thread i: if i < e, count edge; if i < n*50, transpose x [T,N,F] -> xT [N,52]
__global__ void kprep0(const int* __restrict__ dst, int* cnt,
                       const float* __restrict__ x, float* __restrict__ xT,
                       int n, int e) {
    int i = blockIdx.x * blockDim.x + threadIdx.x;
    if (i == 0) g_total = 0;
    if (i < e) atomicAdd(&cnt[dst[i]], 1);
    if (i < n * XREAL) {
        int node = i / XREAL;
        int c = i - node * XREAL;
        int t = c / FIN;
        int f = c - t * FIN;
        xT[(size_t)node * XSTRIDE + c] = x[((size_t)t * n + node) * FIN + f];
    }
}

// per-block scan + single atomic -> contiguous (unordered) slices per node
__global__ __launch_bounds__(256) void koffsets(int* cnt, int n) {
    __shared__ int sh[256];
    __shared__ int sbase;
    int tid = threadIdx.x;
    int i = blockIdx.x * 256 + tid;
    int deg = (i < n) ? cnt[i] : 0;
    sh[tid] = deg;
    __syncthreads();
    for (int off = 1; off < 256; off <<= 1) {
        int t = (tid >= off) ? sh[tid - off] : 0;
        __syncthreads();
        sh[tid] += t;
        __syncthreads();
    }
    if (tid == 255) sbase = atomicAdd(&g_total, sh[255]);
    __syncthreads();
    int start = sbase + sh[tid] - deg;
    if (i < n) {
        g_row[i]    = start;
        g_cursor[i] = start;
        g_deg[i]    = deg;
        cnt[i]      = 0;                 // restore for next replay
        float d = (float)deg + 1.0f;
        g_dis[i]  = rsqrtf(d);
        g_dinv[i] = 1.0f / d;
    }
}

__global__ void kfill(const int* __restrict__ src, const int* __restrict__ dst,
                      const float* __restrict__ dis, int* cursor, int2* edge, int e) {
    int i = blockIdx.x * blockDim.x + threadIdx.x;
    if (i < e) {
        int s = src[i], d = dst[i];
        int pos = atomicAdd(&cursor[d], 1);
        edge[pos] = make_int2(s, __float_as_int(dis[s] * dis[d]));
    }
}

// ---------------- propagation (+ optional fused dense transform) -----------------
// Round-1 proven structure: warp per destination node, lane l owns scalar
// columns {l, l+32, l+64...} (guarded by REALW). Edge meta as one int2 load.
// FUSE: out = relu((S in) @ W + b), W [FIN_IN x 16] applied per time slice.
template <int STRIDE, int REALW, int FIN_IN, int FUSE>
__global__ __launch_bounds__(256) void kprop(const float* __restrict__ in,
                                             float* __restrict__ out,
                                             const int* __restrict__ rowp,
                                             const int* __restrict__ degv,
                                             const int2* __restrict__ edge,
                                             const float* __restrict__ dinv,
                                             const float* __restrict__ Wm,
                                             const float* __restrict__ bm, int n) {
    constexpr int NV = (REALW + 31) / 32;
    __shared__ float sAgg[8][FUSE ? STRIDE : 1];
    __shared__ float sW[FUSE ? FIN_IN * 16 : 1];
    __shared__ float sB[FUSE ? 16 : 1];
    if (FUSE) {
        for (int i = threadIdx.x; i < FIN_IN * 16; i += blockDim.x) sW[i] = Wm[i];
        if (threadIdx.x < 16) sB[threadIdx.x] = bm[threadIdx.x];
        __syncthreads();
    }
    int wwid = threadIdx.x >> 5;
    int node = (blockIdx.x << 3) + wwid;
    if (node >= n) return;
    int lane = threadIdx.x & 31;
    const unsigned FULL = 0xffffffffu;

    float acc[NV];
#pragma unroll
    for (int v = 0; v < NV; v++) acc[v] = 0.f;

    int r0 = rowp[node];
    int deg = degv[node];
    int full = deg & ~31;

    for (int base = r0; base < r0 + full; base += 32) {
        int2 e = edge[base + lane];
#pragma unroll 4
        for (int k = 0; k < 32; k++) {
            int   ss = __shfl_sync(FULL, e.x, k);
            float ww = __int_as_float(__shfl_sync(FULL, e.y, k));
            const float* row = in + (size_t)ss * STRIDE;
#pragma unroll
            for (int v = 0; v < NV; v++) {
                int c = v * 32 + lane;
                float xv = (c < REALW) ? __ldg(row + c) : 0.f;
                acc[v] = fmaf(ww, xv, acc[v]);
            }
        }
    }
    int rem = deg - full;
    if (rem) {
        int base = r0 + full;
        int2 e = make_int2(0, 0);
        if (lane < rem) e = edge[base + lane];
        for (int k = 0; k < rem; k++) {
            int   ss = __shfl_sync(FULL, e.x, k);
            float ww = __int_as_float(__shfl_sync(FULL, e.y, k));
            const float* row = in + (size_t)ss * STRIDE;
#pragma unroll
            for (int v = 0; v < NV; v++) {
                int c = v * 32 + lane;
                float xv = (c < REALW) ? __ldg(row + c) : 0.f;
                acc[v] = fmaf(ww, xv, acc[v]);
            }
        }
    }

    // self-loop
    float di = dinv[node];
    const float* srow = in + (size_t)node * STRIDE;
#pragma unroll
    for (int v = 0; v < NV; v++) {
        int c = v * 32 + lane;
        if (c < REALW) acc[v] = fmaf(di, __ldg(srow + c), acc[v]);
    }

    if (!FUSE) {
        float* orow = out + (size_t)node * STRIDE;
#pragma unroll
        for (int v = 0; v < NV; v++) {
            int c = v * 32 + lane;
            if (c < REALW) orow[c] = acc[v];
        }
        return;
    }

    // fused per-slice transform: out[t*16+h] = relu(b[h] + sum_f agg[t*FIN_IN+f]*W[f,h])
#pragma unroll
    for (int v = 0; v < NV; v++) {
        int c = v * 32 + lane;
        if (c < REALW) sAgg[wwid][c] = acc[v];
    }
    __syncwarp();
    if (lane < 20) {
        int c = lane * 4;         // output col group, 20*4 = 80 outputs
        int t = c >> 4;
        int h = c & 15;
        float o0 = sB[h], o1 = sB[h + 1], o2 = sB[h + 2], o3 = sB[h + 3];
#pragma unroll
        for (int f = 0; f < FIN_IN; f++) {
            float a = sAgg[wwid][t * FIN_IN + f];
            o0 = fmaf(a, sW[f * 16 + h],     o0);
            o1 = fmaf(a, sW[f * 16 + h + 1], o1);
            o2 = fmaf(a, sW[f * 16 + h + 2], o2);
            o3 = fmaf(a, sW[f * 16 + h + 3], o3);
        }
        float4 ov = make_float4(fmaxf(o0, 0.f), fmaxf(o1, 0.f),
                                fmaxf(o2, 0.f), fmaxf(o3, 0.f));
        *((float4*)(out + (size_t)node * FSTRIDE) + lane) = ov;
    }
}

// ---------------- fold gate matmuls: M* = W* @ L*[0:16], B* = b*@L*[0:16] + l* ----
__global__ void kprepG(const float* Wz, const float* bz, const float* Wr, const float* br,
                       const float* Wh, const float* bh,
                       const float* Lz, const float* lz, const float* Lr, const float* lr,
                       const float* Lh, const float* lh) {
    int tid = threadIdx.x;  // 256
    int k = tid >> 4, h = tid & 15;
    float mz = 0.f, mr = 0.f, mh = 0.f;
#pragma unroll
    for (int j = 0; j < 16; j++) {
        mz = fmaf(Wz[k * 16 + j], Lz[j * 16 + h], mz);
        mr = fmaf(Wr[k * 16 + j], Lr[j * 16 + h], mr);
        mh = fmaf(Wh[k * 16 + j], Lh[j * 16 + h], mh);
    }
    g_Mz[tid] = mz; g_Mr[tid] = mr; g_Mh[tid] = mh;
    if (tid < 16) {
        float az = lz[tid], ar = lr[tid], ah = lh[tid];
#pragma unroll
        for (int j = 0; j < 16; j++) {
            az = fmaf(bz[j], Lz[j * 16 + tid], az);
            ar = fmaf(br[j], Lr[j * 16 + tid], ar);
            ah = fmaf(bh[j], Lh[j * 16 + tid], ah);
        }
        g_Bz[tid] = az; g_Br[tid] = ar; g_Bh[tid] = ah;
    }
}

// ---------------- GRU + attention pooling + FC + log_softmax ---------------------
#define GRU_NPB 96
__global__ __launch_bounds__(GRU_NPB) void kgru(const float* __restrict__ P,
                                                const float* __restrict__ Lz,
                                                const float* __restrict__ Lr,
                                                const float* __restrict__ Lh,
                                                const float* __restrict__ att,
                                                const float* __restrict__ fcW,
                                                const float* __restrict__ fcb,
                                                float* __restrict__ out, int n) {
    __shared__ float sP[GRU_NPB * 81];
    __shared__ float sMz[256], sMr[256], sMh[256];
    __shared__ float sLz[256], sLr[256], sLh[256];
    __shared__ float sBz[16], sBr[16], sBh[16];
    __shared__ float sfcW[32], sfcb[2], sprob[TT];

    int tid = threadIdx.x;
    for (int i = tid; i < 256; i += GRU_NPB) {
        sMz[i] = g_Mz[i]; sMr[i] = g_Mr[i]; sMh[i] = g_Mh[i];
        sLz[i] = Lz[256 + i]; sLr[i] = Lr[256 + i]; sLh[i] = Lh[256 + i];
    }
    if (tid < 16) { sBz[tid] = g_Bz[tid]; sBr[tid] = g_Br[tid]; sBh[tid] = g_Bh[tid]; }
    if (tid < 32) sfcW[tid] = fcW[tid];
    if (tid < 2)  sfcb[tid] = fcb[tid];
    if (tid == 0) {
        float m = att[0];
        for (int t = 1; t < TT; t++) m = fmaxf(m, att[t]);
        float ex[TT]; float s = 0.f;
        for (int t = 0; t < TT; t++) { ex[t] = expf(att[t] - m); s += ex[t]; }
        for (int t = 0; t < TT; t++) sprob[t] = ex[t] / s;
    }
    int base = blockIdx.x * GRU_NPB;
    for (int i = tid; i < GRU_NPB * FSTRIDE; i += GRU_NPB) {
        int nd = i / FSTRIDE, c = i - nd * FSTRIDE;
        int g = base + nd;
        sP[nd * 81 + c] = (g < n) ? P[(size_t)g * FSTRIDE + c] : 0.f;
    }
    __syncthreads();

    int node = base + tid;
    if (node >= n) return;
    const float* myP = &sP[tid * 81];

    float H[16], Hacc[16];
#pragma unroll
    for (int h = 0; h < 16; h++) { H[h] = 0.f; Hacc[h] = 0.f; }

#pragma unroll 1
    for (int t = 0; t < TT; t++) {
        float p[16];
#pragma unroll
        for (int k = 0; k < 16; k++) p[k] = myP[t * 16 + k];

        float a[16];
#pragma unroll
        for (int h = 0; h < 16; h++) a[h] = sBz[h];
#pragma unroll
        for (int k = 0; k < 16; k++) {
            float pk = p[k], hk = H[k];
#pragma unroll
            for (int h = 0; h < 16; h++)
                a[h] += pk * sMz[k * 16 + h] + hk * sLz[k * 16 + h];
        }
        float Zg[16];
#pragma unroll
        for (int h = 0; h < 16; h++) Zg[h] = 1.f / (1.f + expf(-a[h]));

#pragma unroll
        for (int h = 0; h < 16; h++) a[h] = sBr[h];
#pragma unroll
        for (int k = 0; k < 16; k++) {
            float pk = p[k], hk = H[k];
#pragma unroll
            for (int h = 0; h < 16; h++)
                a[h] += pk * sMr[k * 16 + h] + hk * sLr[k * 16 + h];
        }
        float Rg[16];
#pragma unroll
        for (int h = 0; h < 16; h++) Rg[h] = 1.f / (1.f + expf(-a[h]));

#pragma unroll
        for (int h = 0; h < 16; h++) a[h] = sBh[h];
#pragma unroll
        for (int k = 0; k < 16; k++) {
            float pk = p[k], hr = H[k] * Rg[k];
#pragma unroll
            for (int h = 0; h < 16; h++)
                a[h] += pk * sMh[k * 16 + h] + hr * sLh[k * 16 + h];
        }
#pragma unroll
        for (int h = 0; h < 16; h++) {
            float ht = tanhf(a[h]);
            H[h] = Zg[h] * H[h] + (1.f - Zg[h]) * ht;
            Hacc[h] = fmaf(sprob[t], H[h], Hacc[h]);
        }
    }

    float l0 = sfcb[0], l1 = sfcb[1];
#pragma unroll
    for (int h = 0; h < 16; h++) {
        l0 = fmaf(Hacc[h], sfcW[h * 2 + 0], l0);
        l1 = fmaf(Hacc[h], sfcW[h * 2 + 1], l1);
    }
    float m = fmaxf(l0, l1);
    float lse = m + logf(expf(l0 - m) + expf(l1 - m));
    out[(size_t)node * 2 + 0] = l0 - lse;
    out[(size_t)node * 2 + 1] = l1 - lse;
}

// ---------------- launch ----------------
extern "C" void kernel_launch(void* const* d_in, const int* in_sizes, int n_in,
                              void* d_out, int out_size) {
    const float* x   = (const float*)d_in[0];
    const int*   src = (const int*)d_in[1];
    const int*   dst = (const int*)d_in[2];
    const float* W1  = (const float*)d_in[3];
    const float* b1  = (const float*)d_in[4];
    const float* W2  = (const float*)d_in[5];
    const float* b2  = (const float*)d_in[6];
    const float* Wz  = (const float*)d_in[7];
    const float* bz  = (const float*)d_in[8];
    const float* Wr  = (const float*)d_in[9];
    const float* br  = (const float*)d_in[10];
    const float* Wh  = (const float*)d_in[11];
    const float* bh  = (const float*)d_in[12];
    const float* Lz  = (const float*)d_in[13];
    const float* lz  = (const float*)d_in[14];
    const float* Lr  = (const float*)d_in[15];
    const float* lr  = (const float*)d_in[16];
    const float* Lh  = (const float*)d_in[17];
    const float* lh  = (const float*)d_in[18];
    const float* att = (const float*)d_in[19];
    const float* fcW = (const float*)d_in[20];
    const float* fcb = (const float*)d_in[21];

    int n = in_sizes[0] / (TT * FIN);
    int e = in_sizes[1];

    void* p;
    cudaGetSymbolAddress(&p, g_cnt);     int*   cnt    = (int*)p;
    cudaGetSymbolAddress(&p, g_deg);     int*   degv   = (int*)p;
    cudaGetSymbolAddress(&p, g_row);     int*   rowp   = (int*)p;
    cudaGetSymbolAddress(&p, g_cursor);  int*   cursor = (int*)p;
    cudaGetSymbolAddress(&p, g_dis);     float* dis    = (float*)p;
    cudaGetSymbolAddress(&p, g_dinv);    float* dinv   = (float*)p;
    cudaGetSymbolAddress(&p, g_edge);    int2*  edge   = (int2*)p;
    cudaGetSymbolAddress(&p, g_xT);      float* xT     = (float*)p;
    cudaGetSymbolAddress(&p, g_h1);      float* h1     = (float*)p;
    cudaGetSymbolAddress(&p, g_feats);   float* feats  = (float*)p;
    cudaGetSymbolAddress(&p, g_P);       float* P      = (float*)p;

    int nb256_n = (n + 255) / 256;
    int nb256_e = (e + 255) / 256;
    int prep0_threads = (e > n * XREAL) ? e : n * XREAL;
    int prop_blocks = (n + 7) / 8;

    // 0: fused degree count + x transpose
    kprep0<<<(prep0_threads + 255) / 256, 256>>>(dst, cnt, x, xT, n, e);
    // 1: offsets + norms
    koffsets<<<nb256_n, 256>>>(cnt, n);
    // 2: fill edge list
    kfill<<<nb256_e, 256>>>(src, dst, dis, cursor, edge, e);
    // 3: h1 = relu((S x) @ W1 + b1)    <-- profiled slot
    kprop<XSTRIDE, XREAL, FIN, 1><<<prop_blocks, 256>>>(xT, h1, rowp, degv, edge, dinv, W1, b1, n);
    // 4: feats = relu((S h1) @ W2 + b2)
    kprop<FSTRIDE, FSTRIDE, HID, 1><<<prop_blocks, 256>>>(h1, feats, rowp, degv, edge, dinv, W2, b2, n);
    // 5: P = S feats (shared by all three GRU gate GCNs)
    kprop<FSTRIDE, FSTRIDE, HID, 0><<<prop_blocks, 256>>>(feats, P, rowp, degv, edge, dinv, W2, b2, n);
    // 6: fold GRU gate weights
    kprepG<<<1, 256>>>(Wz, bz, Wr, br, Wh, bh, Lz, lz, Lr, lr, Lh, lh);
    // 7: GRU + attention + FC + log_softmax
    kgru<<<(n + GRU_NPB - 1) / GRU_NPB, GRU_NPB>>>(P, Lz, Lr, Lh, att, fcW, fcb,
                                                   (float*)d_out, n);
}

// round 4
// speedup vs baseline: 1.3537x; 1.0153x over previous
#include <cuda_runtime.h>
#include <cuda_fp16.h>
#include <math.h>
#include <stdint.h>

// Problem constants (fixed by the dataset)
#define TT 5
#define FIN 10
#define HID 16
#define MAXN 100000
#define MAXE 3200000
#define XSTRIDE 52        // padded T*FIN in halves (50 -> 52)
#define XREAL  50
#define XREAL2 25         // half2 count for width 50
#define FSTRIDE 80        // T*HID
#define FREAL2 40         // half2 count for width 80

// ---------------- device scratch (static: no allocation allowed) ----------------
__device__ int    g_cnt[MAXN];         // zero at load; re-zeroed each call in koffsets
__device__ int    g_deg[MAXN];
__device__ int    g_row[MAXN];
__device__ int    g_cursor[MAXN];
__device__ int    g_total;
__device__ float  g_dis[MAXN];
__device__ float  g_dinv[MAXN];
__device__ int2   g_edge[MAXE];        // .x = src, .y = float bits of enorm
__device__ __half g_xT[(size_t)MAXN * XSTRIDE];
__device__ __half g_h1[(size_t)MAXN * FSTRIDE];
__device__ __half g_feats[(size_t)MAXN * FSTRIDE];
__device__ float  g_P[(size_t)MAXN * FSTRIDE];
__device__ float  g_Mz[256], g_Mr[256], g_Mh[256];
__device__ float  g_Bz[16],  g_Br[16],  g_Bh[16];

// ---------------- stage 0: fused degree count + x transpose (fp16) --------------
__global__ void kprep0(const int* __restrict__ dst, int* cnt,
                       const float* __restrict__ x, __half* __restrict__ xT,
                       int n, int e) {
    int i = blockIdx.x * blockDim.x + threadIdx.x;
    if (i == 0) g_total = 0;
    if (i < e) atomicAdd(&cnt[dst[i]], 1);
    if (i < n * XREAL) {
        int node = i / XREAL;
        int c = i - node * XREAL;
        int t = c / FIN;
        int f = c - t * FIN;
        xT[(size_t)node * XSTRIDE + c] =
            __float2half(x[((size_t)t * n + node) * FIN + f]);
    }
}

// per-block scan + single atomic -> contiguous (unordered) slices per node
__global__ __launch_bounds__(256) void koffsets(int* cnt, int n) {
    __shared__ int sh[256];
    __shared__ int sbase;
    int tid = threadIdx.x;
    int i = blockIdx.x * 256 + tid;
    int deg = (i < n) ? cnt[i] : 0;
    sh[tid] = deg;
    __syncthreads();
    for (int off = 1; off < 256; off <<= 1) {
        int t = (tid >= off) ? sh[tid - off] : 0;
        __syncthreads();
        sh[tid] += t;
        __syncthreads();
    }
    if (tid == 255) sbase = atomicAdd(&g_total, sh[255]);
    __syncthreads();
    int start = sbase + sh[tid] - deg;
    if (i < n) {
        g_row[i]    = start;
        g_cursor[i] = start;
        g_deg[i]    = deg;
        cnt[i]      = 0;                 // restore for next replay
        float d = (float)deg + 1.0f;
        g_dis[i]  = rsqrtf(d);
        g_dinv[i] = 1.0f / d;
    }
}

__global__ void kfill(const int* __restrict__ src, const int* __restrict__ dst,
                      const float* __restrict__ dis, int* cursor, int2* edge, int e) {
    int i = blockIdx.x * blockDim.x + threadIdx.x;
    if (i < e) {
        int s = src[i], d = dst[i];
        int pos = atomicAdd(&cursor[d], 1);
        edge[pos] = make_int2(s, __float_as_int(dis[s] * dis[d]));
    }
}

// ---------------- propagation over fp16 rows (+ optional fused transform) -------
// warp per destination node; lane l owns half2 columns {l, l+32} (guarded REALW2).
// Accumulation fp32. MODE 1: out(half) = relu((S in) @ W + b) per slice, stride 80.
// MODE 0: out(float) = (S in), stride 80.
template <int STRIDE, int REALW2, int FIN_IN, int MODE>
__global__ __launch_bounds__(256) void kprop(const __half* __restrict__ in,
                                             void* __restrict__ outv,
                                             const int* __restrict__ rowp,
                                             const int* __restrict__ degv,
                                             const int2* __restrict__ edge,
                                             const float* __restrict__ dinv,
                                             const float* __restrict__ Wm,
                                             const float* __restrict__ bm, int n) {
    constexpr int NV2 = (REALW2 + 31) / 32;
    __shared__ float sAgg[8][MODE ? REALW2 * 2 : 1];
    __shared__ float sW[MODE ? FIN_IN * 16 : 1];
    __shared__ float sB[MODE ? 16 : 1];
    if (MODE) {
        for (int i = threadIdx.x; i < FIN_IN * 16; i += blockDim.x) sW[i] = Wm[i];
        if (threadIdx.x < 16) sB[threadIdx.x] = bm[threadIdx.x];
        __syncthreads();
    }
    int wwid = threadIdx.x >> 5;
    int node = (blockIdx.x << 3) + wwid;
    if (node >= n) return;
    int lane = threadIdx.x & 31;
    const unsigned FULL = 0xffffffffu;

    float2 acc[NV2];
#pragma unroll
    for (int v = 0; v < NV2; v++) acc[v] = make_float2(0.f, 0.f);

    int r0 = rowp[node];
    int deg = degv[node];
    int full = deg & ~31;

    for (int base = r0; base < r0 + full; base += 32) {
        int2 e = edge[base + lane];
#pragma unroll 4
        for (int k = 0; k < 32; k++) {
            int   ss = __shfl_sync(FULL, e.x, k);
            float ww = __int_as_float(__shfl_sync(FULL, e.y, k));
            const __half2* row = (const __half2*)(in + (size_t)ss * STRIDE);
#pragma unroll
            for (int v = 0; v < NV2; v++) {
                int c2 = v * 32 + lane;
                if (c2 < REALW2) {
                    float2 f = __half22float2(__ldg(row + c2));
                    acc[v].x = fmaf(ww, f.x, acc[v].x);
                    acc[v].y = fmaf(ww, f.y, acc[v].y);
                }
            }
        }
    }
    int rem = deg - full;
    if (rem) {
        int base = r0 + full;
        int2 e = make_int2(0, 0);
        if (lane < rem) e = edge[base + lane];
        for (int k = 0; k < rem; k++) {
            int   ss = __shfl_sync(FULL, e.x, k);
            float ww = __int_as_float(__shfl_sync(FULL, e.y, k));
            const __half2* row = (const __half2*)(in + (size_t)ss * STRIDE);
#pragma unroll
            for (int v = 0; v < NV2; v++) {
                int c2 = v * 32 + lane;
                if (c2 < REALW2) {
                    float2 f = __half22float2(__ldg(row + c2));
                    acc[v].x = fmaf(ww, f.x, acc[v].x);
                    acc[v].y = fmaf(ww, f.y, acc[v].y);
                }
            }
        }
    }

    // self-loop
    float di = dinv[node];
    const __half2* srow = (const __half2*)(in + (size_t)node * STRIDE);
#pragma unroll
    for (int v = 0; v < NV2; v++) {
        int c2 = v * 32 + lane;
        if (c2 < REALW2) {
            float2 f = __half22float2(__ldg(srow + c2));
            acc[v].x = fmaf(di, f.x, acc[v].x);
            acc[v].y = fmaf(di, f.y, acc[v].y);
        }
    }

    if (!MODE) {
        float* orow = (float*)outv + (size_t)node * FSTRIDE;
#pragma unroll
        for (int v = 0; v < NV2; v++) {
            int c2 = v * 32 + lane;
            if (c2 < REALW2) ((float2*)orow)[c2] = acc[v];
        }
        return;
    }

    // fused per-slice transform: out[t*16+h] = relu(b[h] + sum_f agg[t*FIN_IN+f]*W[f,h])
#pragma unroll
    for (int v = 0; v < NV2; v++) {
        int c2 = v * 32 + lane;
        if (c2 < REALW2) {
            sAgg[wwid][2 * c2]     = acc[v].x;
            sAgg[wwid][2 * c2 + 1] = acc[v].y;
        }
    }
    __syncwarp();
    if (lane < 20) {
        int c = lane * 4;         // 20 lanes x 4 outputs = 80
        int t = c >> 4;
        int h = c & 15;
        float o0 = sB[h], o1 = sB[h + 1], o2 = sB[h + 2], o3 = sB[h + 3];
#pragma unroll
        for (int f = 0; f < FIN_IN; f++) {
            float a = sAgg[wwid][t * FIN_IN + f];
            o0 = fmaf(a, sW[f * 16 + h],     o0);
            o1 = fmaf(a, sW[f * 16 + h + 1], o1);
            o2 = fmaf(a, sW[f * 16 + h + 2], o2);
            o3 = fmaf(a, sW[f * 16 + h + 3], o3);
        }
        __half2 p01 = __floats2half2_rn(fmaxf(o0, 0.f), fmaxf(o1, 0.f));
        __half2 p23 = __floats2half2_rn(fmaxf(o2, 0.f), fmaxf(o3, 0.f));
        uint2 pk;
        pk.x = *(unsigned*)&p01;
        pk.y = *(unsigned*)&p23;
        *((uint2*)((__half*)outv + (size_t)node * FSTRIDE) + lane) = pk;
    }
}

// ---------------- fold gate matmuls: M* = W* @ L*[0:16], B* = b*@L*[0:16] + l* ----
__global__ void kprepG(const float* Wz, const float* bz, const float* Wr, const float* br,
                       const float* Wh, const float* bh,
                       const float* Lz, const float* lz, const float* Lr, const float* lr,
                       const float* Lh, const float* lh) {
    int tid = threadIdx.x;  // 256
    int k = tid >> 4, h = tid & 15;
    float mz = 0.f, mr = 0.f, mh = 0.f;
#pragma unroll
    for (int j = 0; j < 16; j++) {
        mz = fmaf(Wz[k * 16 + j], Lz[j * 16 + h], mz);
        mr = fmaf(Wr[k * 16 + j], Lr[j * 16 + h], mr);
        mh = fmaf(Wh[k * 16 + j], Lh[j * 16 + h], mh);
    }
    g_Mz[tid] = mz; g_Mr[tid] = mr; g_Mh[tid] = mh;
    if (tid < 16) {
        float az = lz[tid], ar = lr[tid], ah = lh[tid];
#pragma unroll
        for (int j = 0; j < 16; j++) {
            az = fmaf(bz[j], Lz[j * 16 + tid], az);
            ar = fmaf(br[j], Lr[j * 16 + tid], ar);
            ah = fmaf(bh[j], Lh[j * 16 + tid], ah);
        }
        g_Bz[tid] = az; g_Br[tid] = ar; g_Bh[tid] = ah;
    }
}

// ---------------- GRU + attention pooling + FC + log_softmax ---------------------
#define GRU_NPB 96
__global__ __launch_bounds__(GRU_NPB) void kgru(const float* __restrict__ P,
                                                const float* __restrict__ Lz,
                                                const float* __restrict__ Lr,
                                                const float* __restrict__ Lh,
                                                const float* __restrict__ att,
                                                const float* __restrict__ fcW,
                                                const float* __restrict__ fcb,
                                                float* __restrict__ out, int n) {
    __shared__ float sP[GRU_NPB * 81];
    __shared__ float sMz[256], sMr[256], sMh[256];
    __shared__ float sLz[256], sLr[256], sLh[256];
    __shared__ float sBz[16], sBr[16], sBh[16];
    __shared__ float sfcW[32], sfcb[2], sprob[TT];

    int tid = threadIdx.x;
    for (int i = tid; i < 256; i += GRU_NPB) {
        sMz[i] = g_Mz[i]; sMr[i] = g_Mr[i]; sMh[i] = g_Mh[i];
        sLz[i] = Lz[256 + i]; sLr[i] = Lr[256 + i]; sLh[i] = Lh[256 + i];
    }
    if (tid < 16) { sBz[tid] = g_Bz[tid]; sBr[tid] = g_Br[tid]; sBh[tid] = g_Bh[tid]; }
    if (tid < 32) sfcW[tid] = fcW[tid];
    if (tid < 2)  sfcb[tid] = fcb[tid];
    if (tid == 0) {
        float m = att[0];
        for (int t = 1; t < TT; t++) m = fmaxf(m, att[t]);
        float ex[TT]; float s = 0.f;
        for (int t = 0; t < TT; t++) { ex[t] = expf(att[t] - m); s += ex[t]; }
        for (int t = 0; t < TT; t++) sprob[t] = ex[t] / s;
    }
    int base = blockIdx.x * GRU_NPB;
    for (int i = tid; i < GRU_NPB * FSTRIDE; i += GRU_NPB) {
        int nd = i / FSTRIDE, c = i - nd * FSTRIDE;
        int g = base + nd;
        sP[nd * 81 + c] = (g < n) ? P[(size_t)g * FSTRIDE + c] : 0.f;
    }
    __syncthreads();

    int node = base + tid;
    if (node >= n) return;
    const float* myP = &sP[tid * 81];

    float H[16], Hacc[16];
#pragma unroll
    for (int h = 0; h < 16; h++) { H[h] = 0.f; Hacc[h] = 0.f; }

#pragma unroll 1
    for (int t = 0; t < TT; t++) {
        float p[16];
#pragma unroll
        for (int k = 0; k < 16; k++) p[k] = myP[t * 16 + k];

        float a[16];
#pragma unroll
        for (int h = 0; h < 16; h++) a[h] = sBz[h];
#pragma unroll
        for (int k = 0; k < 16; k++) {
            float pk = p[k], hk = H[k];
#pragma unroll
            for (int h = 0; h < 16; h++)
                a[h] += pk * sMz[k * 16 + h] + hk * sLz[k * 16 + h];
        }
        float Zg[16];
#pragma unroll
        for (int h = 0; h < 16; h++) Zg[h] = 1.f / (1.f + expf(-a[h]));

#pragma unroll
        for (int h = 0; h < 16; h++) a[h] = sBr[h];
#pragma unroll
        for (int k = 0; k < 16; k++) {
            float pk = p[k], hk = H[k];
#pragma unroll
            for (int h = 0; h < 16; h++)
                a[h] += pk * sMr[k * 16 + h] + hk * sLr[k * 16 + h];
        }
        float Rg[16];
#pragma unroll
        for (int h = 0; h < 16; h++) Rg[h] = 1.f / (1.f + expf(-a[h]));

#pragma unroll
        for (int h = 0; h < 16; h++) a[h] = sBh[h];
#pragma unroll
        for (int k = 0; k < 16; k++) {
            float pk = p[k], hr = H[k] * Rg[k];
#pragma unroll
            for (int h = 0; h < 16; h++)
                a[h] += pk * sMh[k * 16 + h] + hr * sLh[k * 16 + h];
        }
#pragma unroll
        for (int h = 0; h < 16; h++) {
            float ht = tanhf(a[h]);
            H[h] = Zg[h] * H[h] + (1.f - Zg[h]) * ht;
            Hacc[h] = fmaf(sprob[t], H[h], Hacc[h]);
        }
    }

    float l0 = sfcb[0], l1 = sfcb[1];
#pragma unroll
    for (int h = 0; h < 16; h++) {
        l0 = fmaf(Hacc[h], sfcW[h * 2 + 0], l0);
        l1 = fmaf(Hacc[h], sfcW[h * 2 + 1], l1);
    }
    float m = fmaxf(l0, l1);
    float lse = m + logf(expf(l0 - m) + expf(l1 - m));
    out[(size_t)node * 2 + 0] = l0 - lse;
    out[(size_t)node * 2 + 1] = l1 - lse;
}

// ---------------- launch ----------------
extern "C" void kernel_launch(void* const* d_in, const int* in_sizes, int n_in,
                              void* d_out, int out_size) {
    const float* x   = (const float*)d_in[0];
    const int*   src = (const int*)d_in[1];
    const int*   dst = (const int*)d_in[2];
    const float* W1  = (const float*)d_in[3];
    const float* b1  = (const float*)d_in[4];
    const float* W2  = (const float*)d_in[5];
    const float* b2  = (const float*)d_in[6];
    const float* Wz  = (const float*)d_in[7];
    const float* bz  = (const float*)d_in[8];
    const float* Wr  = (const float*)d_in[9];
    const float* br  = (const float*)d_in[10];
    const float* Wh  = (const float*)d_in[11];
    const float* bh  = (const float*)d_in[12];
    const float* Lz  = (const float*)d_in[13];
    const float* lz  = (const float*)d_in[14];
    const float* Lr  = (const float*)d_in[15];
    const float* lr  = (const float*)d_in[16];
    const float* Lh  = (const float*)d_in[17];
    const float* lh  = (const float*)d_in[18];
    const float* att = (const float*)d_in[19];
    const float* fcW = (const float*)d_in[20];
    const float* fcb = (const float*)d_in[21];

    int n = in_sizes[0] / (TT * FIN);
    int e = in_sizes[1];

    void* p;
    cudaGetSymbolAddress(&p, g_cnt);     int*    cnt    = (int*)p;
    cudaGetSymbolAddress(&p, g_deg);     int*    degv   = (int*)p;
    cudaGetSymbolAddress(&p, g_row);     int*    rowp   = (int*)p;
    cudaGetSymbolAddress(&p, g_cursor);  int*    cursor = (int*)p;
    cudaGetSymbolAddress(&p, g_dis);     float*  dis    = (float*)p;
    cudaGetSymbolAddress(&p, g_dinv);    float*  dinv   = (float*)p;
    cudaGetSymbolAddress(&p, g_edge);    int2*   edge   = (int2*)p;
    cudaGetSymbolAddress(&p, g_xT);      __half* xT     = (__half*)p;
    cudaGetSymbolAddress(&p, g_h1);      __half* h1     = (__half*)p;
    cudaGetSymbolAddress(&p, g_feats);   __half* feats  = (__half*)p;
    cudaGetSymbolAddress(&p, g_P);       float*  P      = (float*)p;

    int nb256_n = (n + 255) / 256;
    int nb256_e = (e + 255) / 256;
    int prep0_threads = (e > n * XREAL) ? e : n * XREAL;
    int prop_blocks = (n + 7) / 8;

    // 0: fused degree count + x transpose (fp16)
    kprep0<<<(prep0_threads + 255) / 256, 256>>>(dst, cnt, x, xT, n, e);
    // 1: offsets + norms
    koffsets<<<nb256_n, 256>>>(cnt, n);
    // 2: fill edge list
    kfill<<<nb256_e, 256>>>(src, dst, dis, cursor, edge, e);
    // 3: h1 = relu((S x) @ W1 + b1)      <-- profiled slot
    kprop<XSTRIDE, XREAL2, FIN, 1><<<prop_blocks, 256>>>(xT, h1, rowp, degv, edge, dinv, W1, b1, n);
    // 4: feats = relu((S h1) @ W2 + b2)
    kprop<FSTRIDE, FREAL2, HID, 1><<<prop_blocks, 256>>>(h1, feats, rowp, degv, edge, dinv, W2, b2, n);
    // 5: P = S feats (fp32 out, shared by all three GRU gate GCNs)
    kprop<FSTRIDE, FREAL2, HID, 0><<<prop_blocks, 256>>>(feats, P, rowp, degv, edge, dinv, W2, b2, n);
    // 6: fold GRU gate weights
    kprepG<<<1, 256>>>(Wz, bz, Wr, br, Wh, bh, Lz, lz, Lr, lr, Lh, lh);
    // 7: GRU + attention + FC + log_softmax
    kgru<<<(n + GRU_NPB - 1) / GRU_NPB, GRU_NPB>>>(P, Lz, Lr, Lh, att, fcW, fcb,
                                                   (float*)d_out, n);
}